// round 16
// baseline (speedup 1.0000x reference)
#include <cuda_runtime.h>
#include <cstdint>

#define T_STEPS 512
#define B_SZ    64
#define B_HALF  32                 // rows per chain
#define NCHAIN  2                  // independent batch chains
#define NIN     256
#define NHID    1024
#define NOUT    256
#define MROWS   (T_STEPS * B_SZ)   // 32768

#define NTILE   16                 // recurrence n-tiles of 64 cols
#define KSLICE  8                  // recurrence k-slices of 128 k
#define GRID_P  (NTILE * KSLICE)   // 128 persistent blocks (both chains each)

#define CNT_PAD 8

// recurrence smem: W_hi, W_lo (64 x 128) + H fp32 (32 x 128), stride 132
#define RS       132
#define RW_TILE  (64 * RS)
#define RH_TILE  (B_HALF * RS)
#define RN_SMEM  ((2 * RW_TILE + RH_TILE) * 4)   // 84480 bytes

// tgemm smem: A,B each [2][128][36] floats (R9/R11 proven layout)
#define TGS    36
#define TG_BUF (128 * TGS)
#define TG_SMEM (4 * TG_BUF * 4)           // 73728 bytes

// 128 MB scratch for X = relu(IN @ W_in^T + b_in)
__device__ float g_X[(size_t)MROWS * NHID];

// dependency counters: one per (chain, step, n-tile), monotonic forever
__device__ unsigned int g_cnt[NCHAIN * T_STEPS * NTILE * CNT_PAD];
__device__ unsigned long long g_epoch;

__global__ void epoch_bump() { g_epoch += 1ULL; }

// fp32 -> tf32 (round-to-nearest on 10-bit mantissa), kept as fp32 bits
#define TF32R(dst_f, src_f) do {                                      \
    uint32_t _t;                                                      \
    asm("cvt.rna.tf32.f32 %0, %1;" : "=r"(_t) : "f"(src_f));          \
    dst_f = __uint_as_float(_t);                                      \
} while (0)

// same but producing the u32 register directly
#define TF32U(dst_u, src_f) \
    asm("cvt.rna.tf32.f32 %0, %1;" : "=r"(dst_u) : "f"(src_f))

// tf32 tensor-core mma: D(16x8) += A(16x8) * B(8x8), fp32 accum
#define MMA_TF32(d, a, b)                                                     \
    asm volatile(                                                             \
        "mma.sync.aligned.m16n8k8.row.col.f32.tf32.tf32.f32 "                 \
        "{%0,%1,%2,%3}, {%4,%5,%6,%7}, {%8,%9}, {%0,%1,%2,%3};"               \
        : "+f"((d)[0]), "+f"((d)[1]), "+f"((d)[2]), "+f"((d)[3])              \
        : "r"((a)[0]), "r"((a)[1]), "r"((a)[2]), "r"((a)[3]),                 \
          "r"((b)[0]), "r"((b)[1]))

// ===========================================================================
// tf32 mma.sync GEMM (EXACT R9/R11 passing version):
//   C[M,N] = act( A[M,K] @ Bw[N,K]^T + bias1 (+ bias2) )
// ===========================================================================
template <bool RELU, bool TWO_BIAS>
__global__ void __launch_bounds__(256)
tgemm(const float* __restrict__ A, const float* __restrict__ Bw,
      const float* __restrict__ bias1, const float* __restrict__ bias2,
      float* __restrict__ C, int M, int N, int K)
{
    extern __shared__ float sm[];
    float* As = sm;
    float* Bs = sm + 2 * TG_BUF;

    const int tid    = threadIdx.x;
    const int lane   = tid & 31;
    const int wid    = tid >> 5;
    const int warp_m = wid & 1;
    const int warp_n = wid >> 1;

    const int bm = blockIdx.y * 128;
    const int bn = blockIdx.x * 128;

    const float* Ag = A  + (size_t)bm * K;
    const float* Bg = Bw + (size_t)bn * K;

    float4 pa[4], pb[4];
#pragma unroll
    for (int i = 0; i < 4; ++i) {
        const int idx = tid + i * 256, row = idx >> 3, kq = (idx & 7) * 4;
        pa[i] = *(const float4*)(Ag + (size_t)row * K + kq);
        pb[i] = *(const float4*)(Bg + (size_t)row * K + kq);
    }
#pragma unroll
    for (int i = 0; i < 4; ++i) {
        const int idx = tid + i * 256, row = idx >> 3, kq = (idx & 7) * 4;
        float* dA = As + row * TGS + kq;
        float* dB = Bs + row * TGS + kq;
        TF32R(dA[0], pa[i].x); TF32R(dA[1], pa[i].y);
        TF32R(dA[2], pa[i].z); TF32R(dA[3], pa[i].w);
        TF32R(dB[0], pb[i].x); TF32R(dB[1], pb[i].y);
        TF32R(dB[2], pb[i].z); TF32R(dB[3], pb[i].w);
    }
    __syncthreads();

    const int aRow = warp_m * 64 + (lane >> 2);
    const int aCol = lane & 3;
    const int bRow = warp_n * 32 + (lane >> 2);
    const int bCol = lane & 3;

    float acc[4][4][4];
#pragma unroll
    for (int fm = 0; fm < 4; ++fm)
#pragma unroll
        for (int fn = 0; fn < 4; ++fn)
#pragma unroll
            for (int q = 0; q < 4; ++q) acc[fm][fn][q] = 0.f;

    int cur = 0;
    for (int k0 = 0; k0 < K; k0 += 32) {
        const bool more = (k0 + 32 < K);
        if (more) {
#pragma unroll
            for (int i = 0; i < 4; ++i) {
                const int idx = tid + i * 256, row = idx >> 3, kq = (idx & 7) * 4;
                pa[i] = *(const float4*)(Ag + (size_t)row * K + k0 + 32 + kq);
                pb[i] = *(const float4*)(Bg + (size_t)row * K + k0 + 32 + kq);
            }
        }

        const float* Ac = As + cur * TG_BUF;
        const float* Bc = Bs + cur * TG_BUF;
#pragma unroll
        for (int k8 = 0; k8 < 4; ++k8) {
            uint32_t af[4][4], bf[4][2];
#pragma unroll
            for (int fm = 0; fm < 4; ++fm) {
                const float* p = Ac + (aRow + fm * 16) * TGS + k8 * 8 + aCol;
                af[fm][0] = __float_as_uint(p[0]);
                af[fm][1] = __float_as_uint(p[8 * TGS]);
                af[fm][2] = __float_as_uint(p[4]);
                af[fm][3] = __float_as_uint(p[8 * TGS + 4]);
            }
#pragma unroll
            for (int fn = 0; fn < 4; ++fn) {
                const float* p = Bc + (bRow + fn * 8) * TGS + k8 * 8 + bCol;
                bf[fn][0] = __float_as_uint(p[0]);
                bf[fn][1] = __float_as_uint(p[4]);
            }
#pragma unroll
            for (int fm = 0; fm < 4; ++fm)
#pragma unroll
                for (int fn = 0; fn < 4; ++fn)
                    MMA_TF32(acc[fm][fn], af[fm], bf[fn]);
        }

        if (more) {
            const int nxt = cur ^ 1;
#pragma unroll
            for (int i = 0; i < 4; ++i) {
                const int idx = tid + i * 256, row = idx >> 3, kq = (idx & 7) * 4;
                float* dA = As + nxt * TG_BUF + row * TGS + kq;
                float* dB = Bs + nxt * TG_BUF + row * TGS + kq;
                TF32R(dA[0], pa[i].x); TF32R(dA[1], pa[i].y);
                TF32R(dA[2], pa[i].z); TF32R(dA[3], pa[i].w);
                TF32R(dB[0], pb[i].x); TF32R(dB[1], pb[i].y);
                TF32R(dB[2], pb[i].z); TF32R(dB[3], pb[i].w);
            }
        }
        __syncthreads();
        cur ^= 1;
    }

#pragma unroll
    for (int fm = 0; fm < 4; ++fm) {
        const int r = bm + warp_m * 64 + fm * 16 + (lane >> 2);
#pragma unroll
        for (int fn = 0; fn < 4; ++fn) {
            const int c = bn + warp_n * 32 + fn * 8 + 2 * (lane & 3);
            float b0 = bias1[c], b1 = bias1[c + 1];
            if (TWO_BIAS) { b0 += bias2[c]; b1 += bias2[c + 1]; }
            float v0 = acc[fm][fn][0] + b0;
            float v1 = acc[fm][fn][1] + b1;
            float v2 = acc[fm][fn][2] + b0;
            float v3 = acc[fm][fn][3] + b1;
            if (RELU) {
                v0 = fmaxf(v0, 0.f); v1 = fmaxf(v1, 0.f);
                v2 = fmaxf(v2, 0.f); v3 = fmaxf(v3, 0.f);
            }
            *(float2*)(C + (size_t)r * N + c)       = make_float2(v0, v1);
            *(float2*)(C + (size_t)(r + 8) * N + c) = make_float2(v2, v3);
        }
    }
}

// ===========================================================================
// Persistent recurrence v9: interleaved dual-chain per block.
// 128 blocks; each block owns (ntile, kslice) for BOTH chains and alternates
// sub-steps c0-t, c1-t. Each sub-step is the R11-proven body verbatim.
// Chain A's release->consume latency is hidden behind chain B's sub-step.
// W tiles loaded/split once (shared by both chains); single H buffer reused
// (sub-steps are block-serial; pre-release sync fences reuse).
// ===========================================================================
__global__ void __launch_bounds__(256, 2)
rnn_persist(float* __restrict__ hid, const float* __restrict__ Whh)
{
    extern __shared__ float fsmem[];
    float* Whi = fsmem;                  // [64 cols][RS]
    float* Wlo = fsmem + RW_TILE;
    float* Hs  = fsmem + 2 * RW_TILE;    // [32 rows][RS], fp32

    const int tid    = threadIdx.x;
    const int lane   = tid & 31;
    const int wid    = tid >> 5;
    const int warp_m = wid & 1;          // 16-row group within the 32-row chain
    const int warp_n = wid >> 1;         // 0..3 -> 16-col group (2 fn frags)

    const int bid   = blockIdx.x;        // 0..127
    const int ntile = bid % NTILE;
    const int nbase = ntile * 64;
    const int kbase = (bid / NTILE) * 128;
    const int j0    = kbase >> 6;        // first producer n-tile (of 2)

    // ---- load + split W_hh tile ONCE (shared by both chains)
    {
        const int col = tid >> 2;
#pragma unroll
        for (int it = 0; it < 8; ++it) {
            const int k4 = ((tid & 3) + it * 4) * 4;
            float4 w = *(const float4*)(Whh + (size_t)(nbase + col) * NHID + kbase + k4);
            float4 hi, lo;
            TF32R(hi.x, w.x); TF32R(hi.y, w.y); TF32R(hi.z, w.z); TF32R(hi.w, w.w);
            TF32R(lo.x, w.x - hi.x); TF32R(lo.y, w.y - hi.y);
            TF32R(lo.z, w.z - hi.z); TF32R(lo.w, w.w - hi.w);
            *(float4*)(Whi + col * RS + k4) = hi;
            *(float4*)(Wlo + col * RS + k4) = lo;
        }
    }
    __syncthreads();

    const unsigned int target = (unsigned int)(g_epoch * KSLICE);

    const int aRow = warp_m * 16 + (lane >> 2);   // H row within chain
    const int aCol = lane & 3;
    const int bCol = lane & 3;

    for (int t = 1; t < T_STEPS; ++t) {
#pragma unroll
        for (int chain = 0; chain < NCHAIN; ++chain) {
            const int rbase = chain * B_HALF;
            const float* Sprev = hid + (size_t)(t - 1) * B_SZ * NHID;
            float*       Scur  = hid + (size_t)t * B_SZ * NHID;

            // ---- wait for the 2 producer counters of (chain, t-1)
            if (t > 1) {
                if (tid == 0 || tid == 32) {
                    const int jj = (tid == 0) ? j0 : j0 + 1;
                    const unsigned int* cp =
                        &g_cnt[(((size_t)chain * T_STEPS + (t - 1)) * NTILE + jj) * CNT_PAD];
                    unsigned int v;
                    do {
                        asm volatile("ld.relaxed.gpu.global.u32 %0, [%1];"
                                     : "=r"(v) : "l"(cp) : "memory");
                    } while (v < target);
                    asm volatile("ld.acquire.gpu.global.u32 %0, [%1];"
                                 : "=r"(v) : "l"(cp) : "memory");
                }
                __syncthreads();
            }

            // ---- stage relu(S[t-1]) slice [32 rows x 128 k] fp32 into Hs
            {
                const int row = tid >> 3;            // 0..31
#pragma unroll
                for (int it = 0; it < 4; ++it) {
                    const int c4 = ((tid & 7) + it * 8) * 4;
                    float4 v = __ldcg((const float4*)(Sprev +
                                (size_t)(rbase + row) * NHID + kbase + c4));
                    v.x = fmaxf(v.x, 0.f); v.y = fmaxf(v.y, 0.f);
                    v.z = fmaxf(v.z, 0.f); v.w = fmaxf(v.w, 0.f);
                    *(float4*)(Hs + row * RS + c4) = v;
                }
            }
            __syncthreads();

            // ---- 32x16 partial via compensated tensor MMAs (2 fn frags)
            float acc[2][4];
#pragma unroll
            for (int fn = 0; fn < 2; ++fn)
#pragma unroll
                for (int q = 0; q < 4; ++q) acc[fn][q] = 0.f;

#pragma unroll 4
            for (int k8 = 0; k8 < 16; ++k8) {
                const float* p = Hs + aRow * RS + k8 * 8 + aCol;
                float f0 = p[0], f1 = p[8 * RS], f2 = p[4], f3 = p[8 * RS + 4];
                uint32_t ah[4], al[4];
                float h0, h1, h2, h3;
                TF32R(h0, f0); TF32R(h1, f1); TF32R(h2, f2); TF32R(h3, f3);
                ah[0] = __float_as_uint(h0); ah[1] = __float_as_uint(h1);
                ah[2] = __float_as_uint(h2); ah[3] = __float_as_uint(h3);
                TF32U(al[0], f0 - h0); TF32U(al[1], f1 - h1);
                TF32U(al[2], f2 - h2); TF32U(al[3], f3 - h3);
#pragma unroll
                for (int fn = 0; fn < 2; ++fn) {
                    const int brow = warp_n * 16 + fn * 8 + (lane >> 2);
                    const float* pb = Whi + brow * RS + k8 * 8 + bCol;
                    const float* qb = Wlo + brow * RS + k8 * 8 + bCol;
                    uint32_t bh[2], bl[2];
                    bh[0] = __float_as_uint(pb[0]); bh[1] = __float_as_uint(pb[4]);
                    bl[0] = __float_as_uint(qb[0]); bl[1] = __float_as_uint(qb[4]);
                    MMA_TF32(acc[fn], ah, bh);   // hi*hi
                    MMA_TF32(acc[fn], al, bh);   // lo_h*hi_w
                    MMA_TF32(acc[fn], ah, bl);   // hi_h*lo_w
                }
            }

            // ---- combine partials into S[t]: float2 REDs
            {
                const int m = rbase + warp_m * 16 + (lane >> 2);
#pragma unroll
                for (int fn = 0; fn < 2; ++fn) {
                    const int c = nbase + warp_n * 16 + fn * 8 + 2 * (lane & 3);
                    float* p0 = Scur + (size_t)m * NHID + c;
                    float* p1 = Scur + (size_t)(m + 8) * NHID + c;
                    atomicAdd((float2*)p0, make_float2(acc[fn][0], acc[fn][1]));
                    atomicAdd((float2*)p1, make_float2(acc[fn][2], acc[fn][3]));
                }
            }

            // ---- publish this block's (chain, t, ntile) contribution
            __syncthreads();
            if (tid == 0) {
                asm volatile("red.release.gpu.global.add.u32 [%0], %1;"
                             :: "l"(&g_cnt[(((size_t)chain * T_STEPS + t) * NTILE
                                            + ntile) * CNT_PAD]), "r"(1u)
                             : "memory");
            }
        }
    }
}

// ---------------------------------------------------------------------------
__global__ void relu_ip(float* __restrict__ p, int n4)
{
    int stride = gridDim.x * blockDim.x;
    for (int i = blockIdx.x * blockDim.x + threadIdx.x; i < n4; i += stride) {
        float4 v = ((float4*)p)[i];
        v.x = fmaxf(v.x, 0.f);
        v.y = fmaxf(v.y, 0.f);
        v.z = fmaxf(v.z, 0.f);
        v.w = fmaxf(v.w, 0.f);
        ((float4*)p)[i] = v;
    }
}

// ---------------------------------------------------------------------------
extern "C" void kernel_launch(void* const* d_in, const int* in_sizes, int n_in,
                              void* d_out, int out_size)
{
    const float* input = (const float*)d_in[0];
    // d_in[1] = length (fixed 512)
    const float* W_in  = (const float*)d_in[2];
    const float* b_in  = (const float*)d_in[3];
    const float* W_ih  = (const float*)d_in[4];
    const float* b_ih  = (const float*)d_in[5];
    const float* W_hh  = (const float*)d_in[6];
    const float* b_hh  = (const float*)d_in[7];
    const float* W_out = (const float*)d_in[8];
    const float* b_out = (const float*)d_in[9];

    float* hid  = (float*)d_out;                 // [T*B, NHID]
    float* outp = hid + (size_t)MROWS * NHID;    // [T*B, NOUT]

    float* Xp = nullptr;
    cudaGetSymbolAddress((void**)&Xp, g_X);

    cudaFuncSetAttribute(rnn_persist,
                         cudaFuncAttributeMaxDynamicSharedMemorySize, RN_SMEM);
    cudaFuncSetAttribute(tgemm<true,  false>,
                         cudaFuncAttributeMaxDynamicSharedMemorySize, TG_SMEM);
    cudaFuncSetAttribute(tgemm<false, true>,
                         cudaFuncAttributeMaxDynamicSharedMemorySize, TG_SMEM);
    cudaFuncSetAttribute(tgemm<false, false>,
                         cudaFuncAttributeMaxDynamicSharedMemorySize, TG_SMEM);

    // Phase A: X = relu(IN @ W_in^T + b_in)    [32768x1024], K=256 (tf32 TC)
    tgemm<true, false><<<dim3(NHID / 128, MROWS / 128), 256, TG_SMEM>>>(
        input, W_in, b_in, nullptr, Xp, MROWS, NHID, NIN);

    // Phase B: S = X @ W_ih^T + b_ih + b_hh    [32768x1024], K=1024 (tf32 TC)
    tgemm<false, true><<<dim3(NHID / 128, MROWS / 128), 256, TG_SMEM>>>(
        Xp, W_ih, b_ih, b_hh, hid, MROWS, NHID, NHID);

    // Phase C: persistent recurrence — interleaved dual-chain, 128 blocks
    epoch_bump<<<1, 1>>>();
    rnn_persist<<<GRID_P, 256, RN_SMEM>>>(hid, W_hh);

    // Relu fixup: hiddens = relu(S)
    relu_ip<<<8192, 256>>>(hid, (int)((size_t)MROWS * NHID / 4));

    // Phase D: outputs = H @ W_out^T + b_out   [32768x256], K=1024 (tf32 TC)
    tgemm<false, false><<<dim3(NOUT / 128, MROWS / 128), 256, TG_SMEM>>>(
        hid, W_out, b_out, nullptr, outp, MROWS, NOUT, NHID);
}

// round 17
// speedup vs baseline: 1.2179x; 1.2179x over previous
#include <cuda_runtime.h>
#include <cstdint>

#define T_STEPS 512
#define B_SZ    64
#define B_HALF  32                 // rows per chain
#define NCHAIN  2                  // independent batch chains
#define NIN     256
#define NHID    1024
#define NOUT    256
#define MROWS   (T_STEPS * B_SZ)   // 32768

#define NTILE   16                 // recurrence n-tiles of 64 cols
#define KSLICE  8                  // recurrence k-slices of 128 k
#define GRID_P  (NCHAIN * NTILE * KSLICE)   // 256 persistent blocks

#define CNT_PAD 8

// recurrence smem: W_hi, W_lo (64 x 128) + H fp32 (32 x 128), stride 132
#define RS       132
#define RW_TILE  (64 * RS)
#define RH_TILE  (B_HALF * RS)
#define RN_SMEM  ((2 * RW_TILE + RH_TILE) * 4)   // 84480 bytes

// tgemm smem: A,B each [2][128][36] floats
#define TGS    36
#define TG_BUF (128 * TGS)
#define TG_SMEM (4 * TG_BUF * 4)           // 73728 bytes

// 128 MB scratch for X = relu(IN @ W_in^T + b_in)
__device__ float g_X[(size_t)MROWS * NHID];

// dependency counters: one per (chain, step, n-tile), monotonic forever
__device__ unsigned int g_cnt[NCHAIN * T_STEPS * NTILE * CNT_PAD];
__device__ unsigned long long g_epoch;

__global__ void epoch_bump() { g_epoch += 1ULL; }

// fp32 -> tf32 (round-to-nearest on 10-bit mantissa), kept as fp32 bits
#define TF32R(dst_f, src_f) do {                                      \
    uint32_t _t;                                                      \
    asm("cvt.rna.tf32.f32 %0, %1;" : "=r"(_t) : "f"(src_f));          \
    dst_f = __uint_as_float(_t);                                      \
} while (0)

// same but producing the u32 register directly
#define TF32U(dst_u, src_f) \
    asm("cvt.rna.tf32.f32 %0, %1;" : "=r"(dst_u) : "f"(src_f))

// tf32 tensor-core mma: D(16x8) += A(16x8) * B(8x8), fp32 accum
#define MMA_TF32(d, a, b)                                                     \
    asm volatile(                                                             \
        "mma.sync.aligned.m16n8k8.row.col.f32.tf32.tf32.f32 "                 \
        "{%0,%1,%2,%3}, {%4,%5,%6,%7}, {%8,%9}, {%0,%1,%2,%3};"               \
        : "+f"((d)[0]), "+f"((d)[1]), "+f"((d)[2]), "+f"((d)[3])              \
        : "r"((a)[0]), "r"((a)[1]), "r"((a)[2]), "r"((a)[3]),                 \
          "r"((b)[0]), "r"((b)[1]))

// ===========================================================================
// tf32 mma.sync GEMM (R9-proven):
//   C[M,N] = act( A[M,K] @ Bw[N,K]^T + bias1 (+ bias2) )
// 128x128 block tile, BK=32, 256 threads (8 warps, 2x4 grid, 64x32 per warp).
// ===========================================================================
template <bool RELU, bool TWO_BIAS>
__global__ void __launch_bounds__(256)
tgemm(const float* __restrict__ A, const float* __restrict__ Bw,
      const float* __restrict__ bias1, const float* __restrict__ bias2,
      float* __restrict__ C, int M, int N, int K)
{
    extern __shared__ float sm[];
    float* As = sm;
    float* Bs = sm + 2 * TG_BUF;

    const int tid    = threadIdx.x;
    const int lane   = tid & 31;
    const int wid    = tid >> 5;
    const int warp_m = wid & 1;
    const int warp_n = wid >> 1;

    const int bm = blockIdx.y * 128;
    const int bn = blockIdx.x * 128;

    const float* Ag = A  + (size_t)bm * K;
    const float* Bg = Bw + (size_t)bn * K;

    float4 pa[4], pb[4];
#pragma unroll
    for (int i = 0; i < 4; ++i) {
        const int idx = tid + i * 256, row = idx >> 3, kq = (idx & 7) * 4;
        pa[i] = *(const float4*)(Ag + (size_t)row * K + kq);
        pb[i] = *(const float4*)(Bg + (size_t)row * K + kq);
    }
#pragma unroll
    for (int i = 0; i < 4; ++i) {
        const int idx = tid + i * 256, row = idx >> 3, kq = (idx & 7) * 4;
        float* dA = As + row * TGS + kq;
        float* dB = Bs + row * TGS + kq;
        TF32R(dA[0], pa[i].x); TF32R(dA[1], pa[i].y);
        TF32R(dA[2], pa[i].z); TF32R(dA[3], pa[i].w);
        TF32R(dB[0], pb[i].x); TF32R(dB[1], pb[i].y);
        TF32R(dB[2], pb[i].z); TF32R(dB[3], pb[i].w);
    }
    __syncthreads();

    const int aRow = warp_m * 64 + (lane >> 2);
    const int aCol = lane & 3;
    const int bRow = warp_n * 32 + (lane >> 2);
    const int bCol = lane & 3;

    float acc[4][4][4];
#pragma unroll
    for (int fm = 0; fm < 4; ++fm)
#pragma unroll
        for (int fn = 0; fn < 4; ++fn)
#pragma unroll
            for (int q = 0; q < 4; ++q) acc[fm][fn][q] = 0.f;

    int cur = 0;
    for (int k0 = 0; k0 < K; k0 += 32) {
        const bool more = (k0 + 32 < K);
        if (more) {
#pragma unroll
            for (int i = 0; i < 4; ++i) {
                const int idx = tid + i * 256, row = idx >> 3, kq = (idx & 7) * 4;
                pa[i] = *(const float4*)(Ag + (size_t)row * K + k0 + 32 + kq);
                pb[i] = *(const float4*)(Bg + (size_t)row * K + k0 + 32 + kq);
            }
        }

        const float* Ac = As + cur * TG_BUF;
        const float* Bc = Bs + cur * TG_BUF;
#pragma unroll
        for (int k8 = 0; k8 < 4; ++k8) {
            uint32_t af[4][4], bf[4][2];
#pragma unroll
            for (int fm = 0; fm < 4; ++fm) {
                const float* p = Ac + (aRow + fm * 16) * TGS + k8 * 8 + aCol;
                af[fm][0] = __float_as_uint(p[0]);
                af[fm][1] = __float_as_uint(p[8 * TGS]);
                af[fm][2] = __float_as_uint(p[4]);
                af[fm][3] = __float_as_uint(p[8 * TGS + 4]);
            }
#pragma unroll
            for (int fn = 0; fn < 4; ++fn) {
                const float* p = Bc + (bRow + fn * 8) * TGS + k8 * 8 + bCol;
                bf[fn][0] = __float_as_uint(p[0]);
                bf[fn][1] = __float_as_uint(p[4]);
            }
#pragma unroll
            for (int fm = 0; fm < 4; ++fm)
#pragma unroll
                for (int fn = 0; fn < 4; ++fn)
                    MMA_TF32(acc[fm][fn], af[fm], bf[fn]);
        }

        if (more) {
            const int nxt = cur ^ 1;
#pragma unroll
            for (int i = 0; i < 4; ++i) {
                const int idx = tid + i * 256, row = idx >> 3, kq = (idx & 7) * 4;
                float* dA = As + nxt * TG_BUF + row * TGS + kq;
                float* dB = Bs + nxt * TG_BUF + row * TGS + kq;
                TF32R(dA[0], pa[i].x); TF32R(dA[1], pa[i].y);
                TF32R(dA[2], pa[i].z); TF32R(dA[3], pa[i].w);
                TF32R(dB[0], pb[i].x); TF32R(dB[1], pb[i].y);
                TF32R(dB[2], pb[i].z); TF32R(dB[3], pb[i].w);
            }
        }
        __syncthreads();
        cur ^= 1;
    }

#pragma unroll
    for (int fm = 0; fm < 4; ++fm) {
        const int r = bm + warp_m * 64 + fm * 16 + (lane >> 2);
#pragma unroll
        for (int fn = 0; fn < 4; ++fn) {
            const int c = bn + warp_n * 32 + fn * 8 + 2 * (lane & 3);
            float b0 = bias1[c], b1 = bias1[c + 1];
            if (TWO_BIAS) { b0 += bias2[c]; b1 += bias2[c + 1]; }
            float v0 = acc[fm][fn][0] + b0;
            float v1 = acc[fm][fn][1] + b1;
            float v2 = acc[fm][fn][2] + b0;
            float v3 = acc[fm][fn][3] + b1;
            if (RELU) {
                v0 = fmaxf(v0, 0.f); v1 = fmaxf(v1, 0.f);
                v2 = fmaxf(v2, 0.f); v3 = fmaxf(v3, 0.f);
            }
            *(float2*)(C + (size_t)r * N + c)       = make_float2(v0, v1);
            *(float2*)(C + (size_t)(r + 8) * N + c) = make_float2(v2, v3);
        }
    }
}

// ===========================================================================
// Persistent recurrence v5 (R11, best measured: 3150.7us):
// 2 independent batch chains (32 rows each), 256 blocks, 2 blocks/SM,
// tensor-core 3xTF32 compensated MMAs, H staged fp32 with register split.
// ===========================================================================
__global__ void __launch_bounds__(256, 2)
rnn_persist(float* __restrict__ hid, const float* __restrict__ Whh)
{
    extern __shared__ float fsmem[];
    float* Whi = fsmem;                  // [64 cols][RS]
    float* Wlo = fsmem + RW_TILE;
    float* Hs  = fsmem + 2 * RW_TILE;    // [32 rows][RS], fp32

    const int tid    = threadIdx.x;
    const int lane   = tid & 31;
    const int wid    = tid >> 5;
    const int warp_m = wid & 1;          // 16-row group within the 32-row chain
    const int warp_n = wid >> 1;         // 0..3 -> 16-col group (2 fn frags)

    const int bid   = blockIdx.x;
    const int chain = bid >> 7;          // 0 or 1
    const int lb    = bid & 127;
    const int ntile = lb % NTILE;
    const int nbase = ntile * 64;
    const int kbase = (lb / NTILE) * 128;
    const int j0    = kbase >> 6;        // first producer n-tile (of 2)
    const int rbase = chain * B_HALF;    // batch-row base of this chain

    // ---- load + split W_hh tile once: cols [nbase,+64), k [kbase,+128)
    {
        const int col = tid >> 2;
#pragma unroll
        for (int it = 0; it < 8; ++it) {
            const int k4 = ((tid & 3) + it * 4) * 4;
            float4 w = *(const float4*)(Whh + (size_t)(nbase + col) * NHID + kbase + k4);
            float4 hi, lo;
            TF32R(hi.x, w.x); TF32R(hi.y, w.y); TF32R(hi.z, w.z); TF32R(hi.w, w.w);
            TF32R(lo.x, w.x - hi.x); TF32R(lo.y, w.y - hi.y);
            TF32R(lo.z, w.z - hi.z); TF32R(lo.w, w.w - hi.w);
            *(float4*)(Whi + col * RS + k4) = hi;
            *(float4*)(Wlo + col * RS + k4) = lo;
        }
    }
    __syncthreads();

    const unsigned int target = (unsigned int)(g_epoch * KSLICE);

    const int aRow = warp_m * 16 + (lane >> 2);   // H row within chain
    const int aCol = lane & 3;
    const int bCol = lane & 3;

    for (int t = 1; t < T_STEPS; ++t) {
        const float* Sprev = hid + (size_t)(t - 1) * B_SZ * NHID;
        float*       Scur  = hid + (size_t)t * B_SZ * NHID;

        // ---- wait for the 2 producer counters of step t-1 (this chain only)
        if (t > 1) {
            if (tid == 0 || tid == 32) {
                const int jj = (tid == 0) ? j0 : j0 + 1;
                const unsigned int* cp =
                    &g_cnt[(((size_t)chain * T_STEPS + (t - 1)) * NTILE + jj) * CNT_PAD];
                unsigned int v;
                do {
                    asm volatile("ld.relaxed.gpu.global.u32 %0, [%1];"
                                 : "=r"(v) : "l"(cp) : "memory");
                } while (v < target);
                asm volatile("ld.acquire.gpu.global.u32 %0, [%1];"
                             : "=r"(v) : "l"(cp) : "memory");
            }
            __syncthreads();
        }

        // ---- stage relu(S[t-1]) slice [32 rows x 128 k] fp32 into Hs
        {
            const int row = tid >> 3;            // 0..31
#pragma unroll
            for (int it = 0; it < 4; ++it) {
                const int c4 = ((tid & 7) + it * 8) * 4;   // float offset 0..124
                float4 v = __ldcg((const float4*)(Sprev +
                            (size_t)(rbase + row) * NHID + kbase + c4));
                v.x = fmaxf(v.x, 0.f); v.y = fmaxf(v.y, 0.f);
                v.z = fmaxf(v.z, 0.f); v.w = fmaxf(v.w, 0.f);
                *(float4*)(Hs + row * RS + c4) = v;
            }
        }
        __syncthreads();

        // ---- 32x16 partial via compensated tensor MMAs (2 fn frags)
        float acc[2][4];
#pragma unroll
        for (int fn = 0; fn < 2; ++fn)
#pragma unroll
            for (int q = 0; q < 4; ++q) acc[fn][q] = 0.f;

#pragma unroll 4
        for (int k8 = 0; k8 < 16; ++k8) {
            // a fragments: load fp32 H, split hi/lo in registers
            const float* p = Hs + aRow * RS + k8 * 8 + aCol;
            float f0 = p[0], f1 = p[8 * RS], f2 = p[4], f3 = p[8 * RS + 4];
            uint32_t ah[4], al[4];
            float h0, h1, h2, h3;
            TF32R(h0, f0); TF32R(h1, f1); TF32R(h2, f2); TF32R(h3, f3);
            ah[0] = __float_as_uint(h0); ah[1] = __float_as_uint(h1);
            ah[2] = __float_as_uint(h2); ah[3] = __float_as_uint(h3);
            TF32U(al[0], f0 - h0); TF32U(al[1], f1 - h1);
            TF32U(al[2], f2 - h2); TF32U(al[3], f3 - h3);
#pragma unroll
            for (int fn = 0; fn < 2; ++fn) {
                const int brow = warp_n * 16 + fn * 8 + (lane >> 2);
                const float* pb = Whi + brow * RS + k8 * 8 + bCol;
                const float* qb = Wlo + brow * RS + k8 * 8 + bCol;
                uint32_t bh[2], bl[2];
                bh[0] = __float_as_uint(pb[0]); bh[1] = __float_as_uint(pb[4]);
                bl[0] = __float_as_uint(qb[0]); bl[1] = __float_as_uint(qb[4]);
                MMA_TF32(acc[fn], ah, bh);   // hi*hi
                MMA_TF32(acc[fn], al, bh);   // lo_h*hi_w
                MMA_TF32(acc[fn], ah, bl);   // hi_h*lo_w
            }
        }

        // ---- combine partials into S[t]: float2 REDs (rows of this chain)
        {
            const int m = rbase + warp_m * 16 + (lane >> 2);
#pragma unroll
            for (int fn = 0; fn < 2; ++fn) {
                const int c = nbase + warp_n * 16 + fn * 8 + 2 * (lane & 3);
                float* p0 = Scur + (size_t)m * NHID + c;
                float* p1 = Scur + (size_t)(m + 8) * NHID + c;
                atomicAdd((float2*)p0, make_float2(acc[fn][0], acc[fn][1]));
                atomicAdd((float2*)p1, make_float2(acc[fn][2], acc[fn][3]));
            }
        }

        // ---- publish this block's n-tile contribution for step t
        __syncthreads();
        if (tid == 0) {
            asm volatile("red.release.gpu.global.add.u32 [%0], %1;"
                         :: "l"(&g_cnt[(((size_t)chain * T_STEPS + t) * NTILE
                                        + ntile) * CNT_PAD]), "r"(1u)
                         : "memory");
        }
    }
}

// ---------------------------------------------------------------------------
__global__ void relu_ip(float* __restrict__ p, int n4)
{
    int stride = gridDim.x * blockDim.x;
    for (int i = blockIdx.x * blockDim.x + threadIdx.x; i < n4; i += stride) {
        float4 v = ((float4*)p)[i];
        v.x = fmaxf(v.x, 0.f);
        v.y = fmaxf(v.y, 0.f);
        v.z = fmaxf(v.z, 0.f);
        v.w = fmaxf(v.w, 0.f);
        ((float4*)p)[i] = v;
    }
}

// ---------------------------------------------------------------------------
extern "C" void kernel_launch(void* const* d_in, const int* in_sizes, int n_in,
                              void* d_out, int out_size)
{
    const float* input = (const float*)d_in[0];
    // d_in[1] = length (fixed 512)
    const float* W_in  = (const float*)d_in[2];
    const float* b_in  = (const float*)d_in[3];
    const float* W_ih  = (const float*)d_in[4];
    const float* b_ih  = (const float*)d_in[5];
    const float* W_hh  = (const float*)d_in[6];
    const float* b_hh  = (const float*)d_in[7];
    const float* W_out = (const float*)d_in[8];
    const float* b_out = (const float*)d_in[9];

    float* hid  = (float*)d_out;                 // [T*B, NHID]
    float* outp = hid + (size_t)MROWS * NHID;    // [T*B, NOUT]

    float* Xp = nullptr;
    cudaGetSymbolAddress((void**)&Xp, g_X);

    cudaFuncSetAttribute(rnn_persist,
                         cudaFuncAttributeMaxDynamicSharedMemorySize, RN_SMEM);
    cudaFuncSetAttribute(tgemm<true,  false>,
                         cudaFuncAttributeMaxDynamicSharedMemorySize, TG_SMEM);
    cudaFuncSetAttribute(tgemm<false, true>,
                         cudaFuncAttributeMaxDynamicSharedMemorySize, TG_SMEM);
    cudaFuncSetAttribute(tgemm<false, false>,
                         cudaFuncAttributeMaxDynamicSharedMemorySize, TG_SMEM);

    // Phase A: X = relu(IN @ W_in^T + b_in)    [32768x1024], K=256 (tf32 TC)
    tgemm<true, false><<<dim3(NHID / 128, MROWS / 128), 256, TG_SMEM>>>(
        input, W_in, b_in, nullptr, Xp, MROWS, NHID, NIN);

    // Phase B: S = X @ W_ih^T + b_ih + b_hh    [32768x1024], K=1024 (tf32 TC)
    tgemm<false, true><<<dim3(NHID / 128, MROWS / 128), 256, TG_SMEM>>>(
        Xp, W_ih, b_ih, b_hh, hid, MROWS, NHID, NHID);

    // Phase C: persistent recurrence — 2 chains, 256 blocks (R11 best)
    epoch_bump<<<1, 1>>>();
    rnn_persist<<<GRID_P, 256, RN_SMEM>>>(hid, W_hh);

    // Relu fixup: hiddens = relu(S)
    relu_ip<<<8192, 256>>>(hid, (int)((size_t)MROWS * NHID / 4));

    // Phase D: outputs = H @ W_out^T + b_out   [32768x256], K=1024 (tf32 TC)
    tgemm<false, false><<<dim3(NOUT / 128, MROWS / 128), 256, TG_SMEM>>>(
        hid, W_out, b_out, nullptr, outp, MROWS, NOUT, NHID);
}